// round 16
// baseline (speedup 1.0000x reference)
#include <cuda_runtime.h>
#include <cuda_fp16.h>
#include <cstdint>

#define N_NODES 50000
#define NPAD    50176
#define E_EDGES 800000
#define D       256
#define R_REL   8
#define B_BAS   4
#define KPAIR   640           // fp16 pairs per A/W row
#define NR8     (N_NODES * R_REL)   // 400000 (dst,rel) bins
#define NB8     391                 // scan blocks of 1024 bins

// ------------------------------------------------------------------
// Scratch. A as single fp16 pairs (t pairs 0..511, features 512..639).
// W as single fp16 (two buffers, precomputed up front).
// ------------------------------------------------------------------
__device__ __align__(16) uint32_t g_ah1[(size_t)NPAD * KPAIR];
__device__ __align__(16) uint32_t g_ah2[(size_t)NPAD * KPAIR];
__device__ __align__(16) uint32_t g_wb1[(size_t)D * KPAIR];
__device__ __align__(16) uint32_t g_wb2[(size_t)D * KPAIR];
__device__ __align__(16) int      g_cnt [NR8];
__device__ __align__(16) int      g_part[512];
__device__ __align__(16) int      g_rowptr8[NR8 + 1];
__device__ __align__(16) int      g_wcur8[NR8];
__device__ __align__(16) int      g_esrc[E_EDGES];
__device__ int g_scanctr;

// ------------------------------------------------------------------
// helpers
// ------------------------------------------------------------------
__device__ __forceinline__ uint32_t smem_u32(const void* p) {
    uint32_t a;
    asm("{ .reg .u64 t; cvta.to.shared.u64 t, %1; cvt.u32.u64 %0, t; }"
        : "=r"(a) : "l"(p));
    return a;
}

__device__ __forceinline__ uint32_t packh2(float a, float b) {
    __half2 h = __floats2half2_rn(a, b);
    return *(uint32_t*)&h;
}

__device__ __forceinline__ void cp16(uint32_t dst, const void* src) {
    asm volatile("cp.async.cg.shared.global [%0], [%1], 16;" :: "r"(dst), "l"(src));
}

__device__ __forceinline__ void st_cs4(uint32_t* p, uint4 v) {
    asm volatile("st.global.cs.v4.u32 [%0], {%1,%2,%3,%4};"
                 :: "l"(p), "r"(v.x), "r"(v.y), "r"(v.z), "r"(v.w) : "memory");
}

__device__ __forceinline__ void ldsm_x4(uint32_t* r, uint32_t a) {
    asm volatile("ldmatrix.sync.aligned.m8n8.x4.shared.b16 {%0,%1,%2,%3}, [%4];"
        : "=r"(r[0]), "=r"(r[1]), "=r"(r[2]), "=r"(r[3]) : "r"(a));
}

__device__ __forceinline__ void mma_f16(float* c, const uint32_t* a,
                                        uint32_t b0, uint32_t b1) {
    asm volatile(
        "mma.sync.aligned.m16n8k16.row.col.f32.f16.f16.f32 "
        "{%0,%1,%2,%3}, {%4,%5,%6,%7}, {%8,%9}, {%0,%1,%2,%3};"
        : "+f"(c[0]), "+f"(c[1]), "+f"(c[2]), "+f"(c[3])
        : "r"(a[0]), "r"(a[1]), "r"(a[2]), "r"(a[3]), "r"(b0), "r"(b1));
}

// ------------------------------------------------------------------
// Branch A (main stream): pack x features, pack W1, W2.
// ------------------------------------------------------------------
#define CFB  25000
#define WB   640
#define MISCB (CFB + 2 * WB)

__device__ __forceinline__ void prep_w_body(int id, const float* basis,
                                            const float* root, uint32_t* wb) {
    int n = id / KPAIR, kk = id % KPAIR;
    int k0 = kk * 2;
    float x0 = (k0 < 1024) ? basis[(size_t)k0 * D + n]
                           : root[(size_t)(k0 - 1024) * D + n];
    float x1 = (k0 + 1 < 1024) ? basis[(size_t)(k0 + 1) * D + n]
                               : root[(size_t)(k0 + 1 - 1024) * D + n];
    wb[id] = packh2(x0, x1);
}

__global__ void misc_k(const float* __restrict__ x,
                       const float* __restrict__ basis1, const float* __restrict__ root1,
                       const float* __restrict__ basis2, const float* __restrict__ root2) {
    int b = blockIdx.x, t = threadIdx.x;
    if (b < CFB) {
        int id = b * 256 + t;
        int row = id >> 7, p = id & 127;
        float2 v = *(const float2*)(x + (size_t)row * D + p * 2);
        g_ah1[(size_t)row * KPAIR + 512 + p] = packh2(v.x, v.y);
    } else if (b < CFB + WB) {
        prep_w_body((b - CFB) * 256 + t, basis1, root1, g_wb1);
    } else {
        prep_w_body((b - CFB - WB) * 256 + t, basis2, root2, g_wb2);
    }
}

// ------------------------------------------------------------------
// Branch B (stream 2): CSR over (dst*8 + rel) bins
// ------------------------------------------------------------------
__global__ void zero_k() {
    int i = blockIdx.x * blockDim.x + threadIdx.x;
    if (i < NR8) g_cnt[i] = 0;
    if (i == 0) g_scanctr = 0;
}

// 4 edges per thread, int4 loads
__global__ void count_k(const int* __restrict__ ei, const int* __restrict__ et) {
    int q = blockIdx.x * blockDim.x + threadIdx.x;   // quad index
    if (q >= E_EDGES / 4) return;
    int4 d4 = *(const int4*)(ei + E_EDGES + q * 4);
    int4 r4 = *(const int4*)(et + q * 4);
    atomicAdd(&g_cnt[d4.x * R_REL + r4.x], 1);
    atomicAdd(&g_cnt[d4.y * R_REL + r4.y], 1);
    atomicAdd(&g_cnt[d4.z * R_REL + r4.z], 1);
    atomicAdd(&g_cnt[d4.w * R_REL + r4.w], 1);
}

// Fused: per-block sums of g_cnt; last block scans g_part in place.
__global__ void pscan_k() {
    __shared__ int s[256];
    __shared__ int isLast;
    int b = blockIdx.x, t = threadIdx.x;
    int base = b * 1024 + t * 4;
    int sum = 0;
#pragma unroll
    for (int j = 0; j < 4; j++) {
        int idx = base + j;
        if (idx < NR8) sum += g_cnt[idx];
    }
    s[t] = sum;
    __syncthreads();
    for (int o = 128; o > 0; o >>= 1) {
        if (t < o) s[t] += s[t + o];
        __syncthreads();
    }
    if (t == 0) {
        g_part[b] = s[0];
        __threadfence();
        isLast = (atomicAdd(&g_scanctr, 1) == gridDim.x - 1);
    }
    __syncthreads();
    if (!isLast) return;

    // last block: exclusive scan of g_part[0..511] (2 elems/thread)
    __shared__ int sc[512];
    int i0 = t, i1 = t + 256;
    sc[i0] = (i0 < NB8) ? *(volatile int*)&g_part[i0] : 0;
    sc[i1] = (i1 < NB8) ? *(volatile int*)&g_part[i1] : 0;
    __syncthreads();
    for (int o = 1; o < 512; o <<= 1) {
        int v0 = (i0 >= o) ? sc[i0 - o] : 0;
        int v1 = (i1 >= o) ? sc[i1 - o] : 0;
        __syncthreads();
        sc[i0] += v0;
        sc[i1] += v1;
        __syncthreads();
    }
    g_part[i0] = (i0 == 0) ? 0 : sc[i0 - 1];
    g_part[i1] = sc[i1 - 1];
}

__global__ void rowptr8_k() {
    __shared__ int s[256];
    int b = blockIdx.x, t = threadIdx.x;
    int base = b * 1024 + t * 4;
    int v[4];
    int sum = 0;
#pragma unroll
    for (int j = 0; j < 4; j++) {
        int idx = base + j;
        v[j] = (idx < NR8) ? g_cnt[idx] : 0;
        sum += v[j];
    }
    s[t] = sum;
    __syncthreads();
    for (int o = 1; o < 256; o <<= 1) {
        int x = (t >= o) ? s[t - o] : 0;
        __syncthreads();
        s[t] += x;
        __syncthreads();
    }
    int run = g_part[b] + s[t] - sum;
#pragma unroll
    for (int j = 0; j < 4; j++) {
        int idx = base + j;
        if (idx < NR8) {
            g_rowptr8[idx] = run;
            g_wcur8[idx]   = run;
            run += v[j];
            if (idx == NR8 - 1) g_rowptr8[NR8] = run;
        }
    }
}

// 4 edges per thread, int4 loads
__global__ void scatter8_k(const int* __restrict__ ei, const int* __restrict__ et) {
    int q = blockIdx.x * blockDim.x + threadIdx.x;
    if (q >= E_EDGES / 4) return;
    int4 s4 = *(const int4*)(ei + q * 4);
    int4 d4 = *(const int4*)(ei + E_EDGES + q * 4);
    int4 r4 = *(const int4*)(et + q * 4);
    int p;
    p = atomicAdd(&g_wcur8[d4.x * R_REL + r4.x], 1); g_esrc[p] = s4.x;
    p = atomicAdd(&g_wcur8[d4.y * R_REL + r4.y], 1); g_esrc[p] = s4.y;
    p = atomicAdd(&g_wcur8[d4.z * R_REL + r4.z], 1); g_esrc[p] = s4.z;
    p = atomicAdd(&g_wcur8[d4.w * R_REL + r4.w], 1); g_esrc[p] = s4.w;
}

// ------------------------------------------------------------------
// Relation-grouped CSR aggregation (frozen, byte-identical)
// ------------------------------------------------------------------
__global__ __launch_bounds__(256)
void edge_agg_k(const float* __restrict__ comp, int sel) {
    uint32_t* gah = sel ? g_ah2 : g_ah1;
    __shared__ float comp_s[R_REL * B_BAS];
    if (threadIdx.x < R_REL * B_BAS) comp_s[threadIdx.x] = comp[threadIdx.x];
    __syncthreads();

    int dst  = (blockIdx.x * 256 + threadIdx.x) >> 5;
    int lane = threadIdx.x & 31;
    if (dst >= N_NODES) return;

    int rp = (lane <= 8) ? g_rowptr8[dst * R_REL + lane] : 0;

    float acc[B_BAS][8];
#pragma unroll
    for (int b = 0; b < B_BAS; b++)
#pragma unroll
        for (int k = 0; k < 8; k++) acc[b][k] = 0.0f;

    const uint32_t* featbase = gah + 512 + lane * 4;

    for (int r = 0; r < R_REL; r++) {
        int e0 = __shfl_sync(0xFFFFFFFFu, rp, r);
        int e1 = __shfl_sync(0xFFFFFFFFu, rp, r + 1);
        if (e0 >= e1) continue;

        __half2 p0 = __float2half2_rn(0.f), p1 = p0, p2 = p0, p3 = p0;
        int e = e0;
        for (; e + 2 <= e1; e += 2) {
            int s0 = g_esrc[e], s1 = g_esrc[e + 1];
            uint4 q0 = *(const uint4*)(featbase + (size_t)s0 * KPAIR);
            uint4 q1 = *(const uint4*)(featbase + (size_t)s1 * KPAIR);
            p0 = __hadd2(p0, *(__half2*)&q0.x);
            p1 = __hadd2(p1, *(__half2*)&q0.y);
            p2 = __hadd2(p2, *(__half2*)&q0.z);
            p3 = __hadd2(p3, *(__half2*)&q0.w);
            p0 = __hadd2(p0, *(__half2*)&q1.x);
            p1 = __hadd2(p1, *(__half2*)&q1.y);
            p2 = __hadd2(p2, *(__half2*)&q1.z);
            p3 = __hadd2(p3, *(__half2*)&q1.w);
        }
        if (e < e1) {
            int s0 = g_esrc[e];
            uint4 q0 = *(const uint4*)(featbase + (size_t)s0 * KPAIR);
            p0 = __hadd2(p0, *(__half2*)&q0.x);
            p1 = __hadd2(p1, *(__half2*)&q0.y);
            p2 = __hadd2(p2, *(__half2*)&q0.z);
            p3 = __hadd2(p3, *(__half2*)&q0.w);
        }

        float w = 1.0f / (float)(e1 - e0);
        float2 f0 = __half22float2(p0), f1 = __half22float2(p1);
        float2 f2 = __half22float2(p2), f3 = __half22float2(p3);
        const float* cr = comp_s + r * B_BAS;
#pragma unroll
        for (int b = 0; b < B_BAS; b++) {
            float c = cr[b] * w;
            acc[b][0] += c * f0.x; acc[b][1] += c * f0.y;
            acc[b][2] += c * f1.x; acc[b][3] += c * f1.y;
            acc[b][4] += c * f2.x; acc[b][5] += c * f2.y;
            acc[b][6] += c * f3.x; acc[b][7] += c * f3.y;
        }
    }

#pragma unroll
    for (int b = 0; b < B_BAS; b++) {
        uint4 hv;
        hv.x = packh2(acc[b][0], acc[b][1]);
        hv.y = packh2(acc[b][2], acc[b][3]);
        hv.z = packh2(acc[b][4], acc[b][5]);
        hv.w = packh2(acc[b][6], acc[b][7]);
        st_cs4(gah + (size_t)dst * KPAIR + b * 128 + lane * 4, hv);
    }
}

// ------------------------------------------------------------------
// fp16 single-term GEMM — frozen, byte-identical.
// ------------------------------------------------------------------
#define SSTR 20
#define ASZ  (128 * SSTR)
#define GSMEM (4 * ASZ * 4)     // 40960 B

__global__ __launch_bounds__(256, 2)
void gemm_k(int aSel, float* __restrict__ outExt, int mode,
            const float* __restrict__ bias, int M) {
    extern __shared__ uint32_t smem[];
    uint32_t sb = smem_u32(smem);

    const uint32_t* gah = aSel ? g_ah2 : g_ah1;
    const uint32_t* gwb = aSel ? g_wb2 : g_wb1;

    int tid  = threadIdx.x;
    int wid  = tid >> 5, lane = tid & 31;
    int gq   = lane >> 2, t4 = lane & 3;
    int warp_m = wid & 3, warp_n = wid >> 2;
    int row0 = blockIdx.y * 128, c0 = blockIdx.x * 128;

    int rA = (lane & 7) + ((lane >> 3) & 1) * 8;
    int qA = (lane >> 4) * 4;
    int rBrow = ((lane >> 4) & 1) * 8 + (lane & 7);
    int hB    = ((lane >> 3) & 1) * 4;

    float acc[2][8][4];
#pragma unroll
    for (int mb = 0; mb < 2; mb++)
#pragma unroll
        for (int nb = 0; nb < 8; nb++)
#pragma unroll
            for (int c = 0; c < 4; c++) acc[mb][nb][c] = 0.0f;

#define PREFETCH(kc, buf) do {                                                \
    int _kc = (kc), _b = (buf);                                               \
    uint32_t bA  = sb + (uint32_t)((_b * 2 + 0) * ASZ) * 4;                   \
    uint32_t bBh = sb + (uint32_t)((_b * 2 + 1) * ASZ) * 4;                   \
    _Pragma("unroll")                                                         \
    for (int f = 0; f < 2; f++) {                                             \
        int id = tid + f * 256;                                               \
        int row = id >> 2, q = id & 3;                                        \
        uint32_t doff = (uint32_t)(row * SSTR + q * 4) * 4;                   \
        size_t ga = (size_t)(row0 + row) * KPAIR + _kc * 16 + q * 4;          \
        cp16(bA + doff, gah + ga);                                            \
        size_t gb = (size_t)(c0 + row) * KPAIR + _kc * 16 + q * 4;            \
        cp16(bBh + doff, gwb + gb);                                           \
    }                                                                         \
} while (0)

    const int NC = KPAIR / 16;   // 40
    PREFETCH(0, 0);
    asm volatile("cp.async.commit_group;" ::: "memory");

    for (int kc = 0; kc < NC; kc++) {
        if (kc + 1 < NC) {
            PREFETCH(kc + 1, (kc + 1) & 1);
            asm volatile("cp.async.commit_group;" ::: "memory");
            asm volatile("cp.async.wait_group 1;" ::: "memory");
        } else {
            asm volatile("cp.async.wait_group 0;" ::: "memory");
        }
        __syncthreads();

        int buf = kc & 1;
        uint32_t bA  = sb + (uint32_t)((buf * 2 + 0) * ASZ) * 4;
        uint32_t bBH = sb + (uint32_t)((buf * 2 + 1) * ASZ) * 4;

#pragma unroll
        for (int s = 0; s < 2; s++) {
            uint32_t ah[2][4];
#pragma unroll
            for (int mb = 0; mb < 2; mb++) {
                uint32_t off = (uint32_t)((warp_m * 32 + mb * 16 + rA) * SSTR
                                          + s * 8 + qA) * 4;
                ldsm_x4(ah[mb], bA + off);
            }
#pragma unroll
            for (int nb2 = 0; nb2 < 4; nb2++) {
                uint32_t offb = (uint32_t)((warp_n * 64 + nb2 * 16 + rBrow) * SSTR
                                           + s * 8 + hB) * 4;
                uint32_t bh[4];
                ldsm_x4(bh, bBH + offb);
#pragma unroll
                for (int half = 0; half < 2; half++) {
                    int nb = nb2 * 2 + half;
#pragma unroll
                    for (int mb = 0; mb < 2; mb++) {
                        mma_f16(acc[mb][nb], ah[mb], bh[half * 2], bh[half * 2 + 1]);
                    }
                }
            }
        }
        __syncthreads();
    }

    // ---- epilogue ----
#pragma unroll
    for (int nb = 0; nb < 8; nb++) {
        int coll = warp_n * 64 + nb * 8 + t4 * 2;
        float2 bv = *(const float2*)(bias + c0 + coll);
#pragma unroll
        for (int mb = 0; mb < 2; mb++) {
            int r0 = row0 + warp_m * 32 + mb * 16 + gq;
            int r1 = r0 + 8;
            float x0 = acc[mb][nb][0] + bv.x, x1 = acc[mb][nb][1] + bv.y;
            float x2 = acc[mb][nb][2] + bv.x, x3 = acc[mb][nb][3] + bv.y;
            if (mode == 1) {
                x0 = fmaxf(x0, 0.f); x1 = fmaxf(x1, 0.f);
                x2 = fmaxf(x2, 0.f); x3 = fmaxf(x3, 0.f);
                int p = (1024 + c0 + coll) >> 1;
                if (r0 < M) g_ah2[(size_t)r0 * KPAIR + p] = packh2(x0, x1);
                if (r1 < M) g_ah2[(size_t)r1 * KPAIR + p] = packh2(x2, x3);
            } else {
                if (r0 < M) *(float2*)(outExt + (size_t)r0 * D + c0 + coll) = make_float2(x0, x1);
                if (r1 < M) *(float2*)(outExt + (size_t)r1 * D + c0 + coll) = make_float2(x2, x3);
            }
        }
    }
}

// ------------------------------------------------------------------
extern "C" void kernel_launch(void* const* d_in, const int* in_sizes, int n_in,
                              void* d_out, int out_size) {
    const float* x      = (const float*)d_in[0];
    const int*   ei     = (const int*)d_in[1];
    const int*   et     = (const int*)d_in[2];
    const float* basis1 = (const float*)d_in[3];
    const float* comp1  = (const float*)d_in[4];
    const float* root1  = (const float*)d_in[5];
    const float* bias1  = (const float*)d_in[6];
    const float* basis2 = (const float*)d_in[7];
    const float* comp2  = (const float*)d_in[8];
    const float* root2  = (const float*)d_in[9];
    const float* bias2  = (const float*)d_in[10];
    float* out = (float*)d_out;

    static cudaStream_t s2;
    static cudaEvent_t evFork, evJoin;
    static bool init = false;
    if (!init) {
        cudaStreamCreateWithFlags(&s2, cudaStreamNonBlocking);
        cudaEventCreateWithFlags(&evFork, cudaEventDisableTiming);
        cudaEventCreateWithFlags(&evJoin, cudaEventDisableTiming);
        cudaFuncSetAttribute(gemm_k, cudaFuncAttributeMaxDynamicSharedMemorySize, GSMEM);
        init = true;
    }

    const int T = 256;
    const int EQ = E_EDGES / 4;

    // ---- fork: CSR chain on s2, feature/W packing on main stream ----
    cudaEventRecord(evFork, 0);
    cudaStreamWaitEvent(s2, evFork, 0);

    zero_k<<<(NR8 + T - 1) / T, T, 0, s2>>>();
    count_k<<<(EQ + T - 1) / T, T, 0, s2>>>(ei, et);
    pscan_k<<<NB8, 256, 0, s2>>>();
    rowptr8_k<<<NB8, 256, 0, s2>>>();
    scatter8_k<<<(EQ + T - 1) / T, T, 0, s2>>>(ei, et);
    cudaEventRecord(evJoin, s2);

    misc_k<<<MISCB, T>>>(x, basis1, root1, basis2, root2);   // main stream

    // ---- join ----
    cudaStreamWaitEvent(0, evJoin, 0);

    dim3 gG(2, (N_NODES + 127) / 128);
    int aggBlocks = (N_NODES * 32 + T - 1) / T;

    // ---------------- layer 1 ----------------
    edge_agg_k<<<aggBlocks, T>>>(comp1, 0);
    gemm_k<<<gG, T, GSMEM>>>(0, nullptr, 1, bias1, N_NODES);

    // ---------------- layer 2 ----------------
    edge_agg_k<<<aggBlocks, T>>>(comp2, 1);
    gemm_k<<<gG, T, GSMEM>>>(1, out, 0, bias2, N_NODES);
}

// round 17
// speedup vs baseline: 1.0137x; 1.0137x over previous
#include <cuda_runtime.h>
#include <cuda_fp16.h>
#include <cstdint>

#define N_NODES 50000
#define NPAD    50176
#define E_EDGES 800000
#define D       256
#define R_REL   8
#define B_BAS   4
#define KPAIR   640           // fp16 pairs per A/W row
#define NR8     (N_NODES * R_REL)   // 400000 (dst,rel) bins
#define NB8     391                 // scan blocks of 1024 bins

// ------------------------------------------------------------------
// Scratch. A as single fp16 pairs (t pairs 0..511, features 512..639).
// W as single fp16 (two buffers, precomputed up front).
// ------------------------------------------------------------------
__device__ __align__(16) uint32_t g_ah1[(size_t)NPAD * KPAIR];
__device__ __align__(16) uint32_t g_ah2[(size_t)NPAD * KPAIR];
__device__ __align__(16) uint32_t g_wb1[(size_t)D * KPAIR];
__device__ __align__(16) uint32_t g_wb2[(size_t)D * KPAIR];
__device__ __align__(16) int      g_cnt [NR8];
__device__ __align__(16) int      g_part[512];
__device__ __align__(16) int      g_rowptr8[NR8 + 1];
__device__ __align__(16) int      g_wcur8[NR8];
__device__ __align__(16) int      g_esrc[E_EDGES];

// ------------------------------------------------------------------
// helpers
// ------------------------------------------------------------------
__device__ __forceinline__ uint32_t smem_u32(const void* p) {
    uint32_t a;
    asm("{ .reg .u64 t; cvta.to.shared.u64 t, %1; cvt.u32.u64 %0, t; }"
        : "=r"(a) : "l"(p));
    return a;
}

__device__ __forceinline__ uint32_t packh2(float a, float b) {
    __half2 h = __floats2half2_rn(a, b);
    return *(uint32_t*)&h;
}

__device__ __forceinline__ void cp16(uint32_t dst, const void* src) {
    asm volatile("cp.async.cg.shared.global [%0], [%1], 16;" :: "r"(dst), "l"(src));
}

__device__ __forceinline__ void st_cs4(uint32_t* p, uint4 v) {
    asm volatile("st.global.cs.v4.u32 [%0], {%1,%2,%3,%4};"
                 :: "l"(p), "r"(v.x), "r"(v.y), "r"(v.z), "r"(v.w) : "memory");
}

__device__ __forceinline__ void ldsm_x4(uint32_t* r, uint32_t a) {
    asm volatile("ldmatrix.sync.aligned.m8n8.x4.shared.b16 {%0,%1,%2,%3}, [%4];"
        : "=r"(r[0]), "=r"(r[1]), "=r"(r[2]), "=r"(r[3]) : "r"(a));
}

__device__ __forceinline__ void mma_f16(float* c, const uint32_t* a,
                                        uint32_t b0, uint32_t b1) {
    asm volatile(
        "mma.sync.aligned.m16n8k16.row.col.f32.f16.f16.f32 "
        "{%0,%1,%2,%3}, {%4,%5,%6,%7}, {%8,%9}, {%0,%1,%2,%3};"
        : "+f"(c[0]), "+f"(c[1]), "+f"(c[2]), "+f"(c[3])
        : "r"(a[0]), "r"(a[1]), "r"(a[2]), "r"(a[3]), "r"(b0), "r"(b1));
}

// ------------------------------------------------------------------
// Branch A (main stream): pack x features, pack W1, W2.
// ------------------------------------------------------------------
#define CFB  25000
#define WB   640
#define MISCB (CFB + 2 * WB)

__device__ __forceinline__ void prep_w_body(int id, const float* basis,
                                            const float* root, uint32_t* wb) {
    int n = id / KPAIR, kk = id % KPAIR;
    int k0 = kk * 2;
    float x0 = (k0 < 1024) ? basis[(size_t)k0 * D + n]
                           : root[(size_t)(k0 - 1024) * D + n];
    float x1 = (k0 + 1 < 1024) ? basis[(size_t)(k0 + 1) * D + n]
                               : root[(size_t)(k0 + 1 - 1024) * D + n];
    wb[id] = packh2(x0, x1);
}

__global__ void misc_k(const float* __restrict__ x,
                       const float* __restrict__ basis1, const float* __restrict__ root1,
                       const float* __restrict__ basis2, const float* __restrict__ root2) {
    int b = blockIdx.x, t = threadIdx.x;
    if (b < CFB) {
        int id = b * 256 + t;
        int row = id >> 7, p = id & 127;
        float2 v = *(const float2*)(x + (size_t)row * D + p * 2);
        g_ah1[(size_t)row * KPAIR + 512 + p] = packh2(v.x, v.y);
    } else if (b < CFB + WB) {
        prep_w_body((b - CFB) * 256 + t, basis1, root1, g_wb1);
    } else {
        prep_w_body((b - CFB - WB) * 256 + t, basis2, root2, g_wb2);
    }
}

// ------------------------------------------------------------------
// Branch B (stream 2): CSR over (dst*8 + rel) bins
// ------------------------------------------------------------------
__global__ void zero_k() {
    int i = blockIdx.x * blockDim.x + threadIdx.x;
    if (i < NR8) g_cnt[i] = 0;
}

__global__ void count_k(const int* __restrict__ ei, const int* __restrict__ et) {
    int e = blockIdx.x * blockDim.x + threadIdx.x;
    if (e >= E_EDGES) return;
    atomicAdd(&g_cnt[ei[E_EDGES + e] * R_REL + et[e]], 1);
}

__global__ void partial8_k() {
    __shared__ int s[256];
    int b = blockIdx.x, t = threadIdx.x;
    int base = b * 1024 + t * 4;
    int sum = 0;
#pragma unroll
    for (int j = 0; j < 4; j++) {
        int idx = base + j;
        if (idx < NR8) sum += g_cnt[idx];
    }
    s[t] = sum;
    __syncthreads();
    for (int o = 128; o > 0; o >>= 1) {
        if (t < o) s[t] += s[t + o];
        __syncthreads();
    }
    if (t == 0) g_part[b] = s[0];
}

__global__ void scanp8_k() {
    __shared__ int s[512];
    int t = threadIdx.x;
    s[t] = (t < NB8) ? g_part[t] : 0;
    __syncthreads();
    for (int o = 1; o < 512; o <<= 1) {
        int v = (t >= o) ? s[t - o] : 0;
        __syncthreads();
        s[t] += v;
        __syncthreads();
    }
    g_part[t] = (t == 0) ? 0 : s[t - 1];
}

__global__ void rowptr8_k() {
    __shared__ int s[256];
    int b = blockIdx.x, t = threadIdx.x;
    int base = b * 1024 + t * 4;
    int v[4];
    int sum = 0;
#pragma unroll
    for (int j = 0; j < 4; j++) {
        int idx = base + j;
        v[j] = (idx < NR8) ? g_cnt[idx] : 0;
        sum += v[j];
    }
    s[t] = sum;
    __syncthreads();
    for (int o = 1; o < 256; o <<= 1) {
        int x = (t >= o) ? s[t - o] : 0;
        __syncthreads();
        s[t] += x;
        __syncthreads();
    }
    int run = g_part[b] + s[t] - sum;
#pragma unroll
    for (int j = 0; j < 4; j++) {
        int idx = base + j;
        if (idx < NR8) {
            g_rowptr8[idx] = run;
            g_wcur8[idx]   = run;
            run += v[j];
            if (idx == NR8 - 1) g_rowptr8[NR8] = run;
        }
    }
}

__global__ void scatter8_k(const int* __restrict__ ei, const int* __restrict__ et) {
    int e = blockIdx.x * blockDim.x + threadIdx.x;
    if (e >= E_EDGES) return;
    int src = ei[e];
    int dst = ei[E_EDGES + e];
    int r   = et[e];
    int pos = atomicAdd(&g_wcur8[dst * R_REL + r], 1);
    g_esrc[pos] = src;
}

// ------------------------------------------------------------------
// Relation-grouped CSR aggregation (frozen, byte-identical)
// ------------------------------------------------------------------
__global__ __launch_bounds__(256)
void edge_agg_k(const float* __restrict__ comp, int sel) {
    uint32_t* gah = sel ? g_ah2 : g_ah1;
    __shared__ float comp_s[R_REL * B_BAS];
    if (threadIdx.x < R_REL * B_BAS) comp_s[threadIdx.x] = comp[threadIdx.x];
    __syncthreads();

    int dst  = (blockIdx.x * 256 + threadIdx.x) >> 5;
    int lane = threadIdx.x & 31;
    if (dst >= N_NODES) return;

    int rp = (lane <= 8) ? g_rowptr8[dst * R_REL + lane] : 0;

    float acc[B_BAS][8];
#pragma unroll
    for (int b = 0; b < B_BAS; b++)
#pragma unroll
        for (int k = 0; k < 8; k++) acc[b][k] = 0.0f;

    const uint32_t* featbase = gah + 512 + lane * 4;

    for (int r = 0; r < R_REL; r++) {
        int e0 = __shfl_sync(0xFFFFFFFFu, rp, r);
        int e1 = __shfl_sync(0xFFFFFFFFu, rp, r + 1);
        if (e0 >= e1) continue;

        __half2 p0 = __float2half2_rn(0.f), p1 = p0, p2 = p0, p3 = p0;
        int e = e0;
        for (; e + 2 <= e1; e += 2) {
            int s0 = g_esrc[e], s1 = g_esrc[e + 1];
            uint4 q0 = *(const uint4*)(featbase + (size_t)s0 * KPAIR);
            uint4 q1 = *(const uint4*)(featbase + (size_t)s1 * KPAIR);
            p0 = __hadd2(p0, *(__half2*)&q0.x);
            p1 = __hadd2(p1, *(__half2*)&q0.y);
            p2 = __hadd2(p2, *(__half2*)&q0.z);
            p3 = __hadd2(p3, *(__half2*)&q0.w);
            p0 = __hadd2(p0, *(__half2*)&q1.x);
            p1 = __hadd2(p1, *(__half2*)&q1.y);
            p2 = __hadd2(p2, *(__half2*)&q1.z);
            p3 = __hadd2(p3, *(__half2*)&q1.w);
        }
        if (e < e1) {
            int s0 = g_esrc[e];
            uint4 q0 = *(const uint4*)(featbase + (size_t)s0 * KPAIR);
            p0 = __hadd2(p0, *(__half2*)&q0.x);
            p1 = __hadd2(p1, *(__half2*)&q0.y);
            p2 = __hadd2(p2, *(__half2*)&q0.z);
            p3 = __hadd2(p3, *(__half2*)&q0.w);
        }

        float w = 1.0f / (float)(e1 - e0);
        float2 f0 = __half22float2(p0), f1 = __half22float2(p1);
        float2 f2 = __half22float2(p2), f3 = __half22float2(p3);
        const float* cr = comp_s + r * B_BAS;
#pragma unroll
        for (int b = 0; b < B_BAS; b++) {
            float c = cr[b] * w;
            acc[b][0] += c * f0.x; acc[b][1] += c * f0.y;
            acc[b][2] += c * f1.x; acc[b][3] += c * f1.y;
            acc[b][4] += c * f2.x; acc[b][5] += c * f2.y;
            acc[b][6] += c * f3.x; acc[b][7] += c * f3.y;
        }
    }

#pragma unroll
    for (int b = 0; b < B_BAS; b++) {
        uint4 hv;
        hv.x = packh2(acc[b][0], acc[b][1]);
        hv.y = packh2(acc[b][2], acc[b][3]);
        hv.z = packh2(acc[b][4], acc[b][5]);
        hv.w = packh2(acc[b][6], acc[b][7]);
        st_cs4(gah + (size_t)dst * KPAIR + b * 128 + lane * 4, hv);
    }
}

// ------------------------------------------------------------------
// fp16 single-term GEMM — 3-stage cp.async ring (single variable vs
// the 426.9 champion; chunk size / fragments / mma unchanged).
// ------------------------------------------------------------------
#define SSTR 20
#define ASZ  (128 * SSTR)
#define GSMEM (6 * ASZ * 4)     // 3 stages x (A + B) = 61440 B

__global__ __launch_bounds__(256, 2)
void gemm_k(int aSel, float* __restrict__ outExt, int mode,
            const float* __restrict__ bias, int M) {
    extern __shared__ uint32_t smem[];
    uint32_t sb = smem_u32(smem);

    const uint32_t* gah = aSel ? g_ah2 : g_ah1;
    const uint32_t* gwb = aSel ? g_wb2 : g_wb1;

    int tid  = threadIdx.x;
    int wid  = tid >> 5, lane = tid & 31;
    int gq   = lane >> 2, t4 = lane & 3;
    int warp_m = wid & 3, warp_n = wid >> 2;
    int row0 = blockIdx.y * 128, c0 = blockIdx.x * 128;

    int rA = (lane & 7) + ((lane >> 3) & 1) * 8;
    int qA = (lane >> 4) * 4;
    int rBrow = ((lane >> 4) & 1) * 8 + (lane & 7);
    int hB    = ((lane >> 3) & 1) * 4;

    float acc[2][8][4];
#pragma unroll
    for (int mb = 0; mb < 2; mb++)
#pragma unroll
        for (int nb = 0; nb < 8; nb++)
#pragma unroll
            for (int c = 0; c < 4; c++) acc[mb][nb][c] = 0.0f;

#define PREFETCH(kc, buf) do {                                                \
    int _kc = (kc), _b = (buf);                                               \
    uint32_t bA  = sb + (uint32_t)((_b * 2 + 0) * ASZ) * 4;                   \
    uint32_t bBh = sb + (uint32_t)((_b * 2 + 1) * ASZ) * 4;                   \
    _Pragma("unroll")                                                         \
    for (int f = 0; f < 2; f++) {                                             \
        int id = tid + f * 256;                                               \
        int row = id >> 2, q = id & 3;                                        \
        uint32_t doff = (uint32_t)(row * SSTR + q * 4) * 4;                   \
        size_t ga = (size_t)(row0 + row) * KPAIR + _kc * 16 + q * 4;          \
        cp16(bA + doff, gah + ga);                                            \
        size_t gb = (size_t)(c0 + row) * KPAIR + _kc * 16 + q * 4;            \
        cp16(bBh + doff, gwb + gb);                                           \
    }                                                                         \
} while (0)

    const int NC = KPAIR / 16;   // 40
    PREFETCH(0, 0);
    asm volatile("cp.async.commit_group;" ::: "memory");
    PREFETCH(1, 1);
    asm volatile("cp.async.commit_group;" ::: "memory");

    int buf = 0;
    for (int kc = 0; kc < NC; kc++) {
        if (kc + 1 < NC) {
            asm volatile("cp.async.wait_group 1;" ::: "memory");
        } else {
            asm volatile("cp.async.wait_group 0;" ::: "memory");
        }
        __syncthreads();   // chunk kc visible; all warps done with buf (kc-1)%3

        if (kc + 2 < NC) {
            int nb3 = buf + 2; if (nb3 >= 3) nb3 -= 3;   // (kc+2)%3 == (kc-1)%3
            PREFETCH(kc + 2, nb3);
            asm volatile("cp.async.commit_group;" ::: "memory");
        }

        uint32_t bA  = sb + (uint32_t)((buf * 2 + 0) * ASZ) * 4;
        uint32_t bBH = sb + (uint32_t)((buf * 2 + 1) * ASZ) * 4;

#pragma unroll
        for (int s = 0; s < 2; s++) {
            uint32_t ah[2][4];
#pragma unroll
            for (int mb = 0; mb < 2; mb++) {
                uint32_t off = (uint32_t)((warp_m * 32 + mb * 16 + rA) * SSTR
                                          + s * 8 + qA) * 4;
                ldsm_x4(ah[mb], bA + off);
            }
#pragma unroll
            for (int nb2 = 0; nb2 < 4; nb2++) {
                uint32_t offb = (uint32_t)((warp_n * 64 + nb2 * 16 + rBrow) * SSTR
                                           + s * 8 + hB) * 4;
                uint32_t bh[4];
                ldsm_x4(bh, bBH + offb);
#pragma unroll
                for (int half = 0; half < 2; half++) {
                    int nb = nb2 * 2 + half;
#pragma unroll
                    for (int mb = 0; mb < 2; mb++) {
                        mma_f16(acc[mb][nb], ah[mb], bh[half * 2], bh[half * 2 + 1]);
                    }
                }
            }
        }
        if (++buf == 3) buf = 0;
    }

    // ---- epilogue ----
#pragma unroll
    for (int nb = 0; nb < 8; nb++) {
        int coll = warp_n * 64 + nb * 8 + t4 * 2;
        float2 bv = *(const float2*)(bias + c0 + coll);
#pragma unroll
        for (int mb = 0; mb < 2; mb++) {
            int r0 = row0 + warp_m * 32 + mb * 16 + gq;
            int r1 = r0 + 8;
            float x0 = acc[mb][nb][0] + bv.x, x1 = acc[mb][nb][1] + bv.y;
            float x2 = acc[mb][nb][2] + bv.x, x3 = acc[mb][nb][3] + bv.y;
            if (mode == 1) {
                x0 = fmaxf(x0, 0.f); x1 = fmaxf(x1, 0.f);
                x2 = fmaxf(x2, 0.f); x3 = fmaxf(x3, 0.f);
                int p = (1024 + c0 + coll) >> 1;
                if (r0 < M) g_ah2[(size_t)r0 * KPAIR + p] = packh2(x0, x1);
                if (r1 < M) g_ah2[(size_t)r1 * KPAIR + p] = packh2(x2, x3);
            } else {
                if (r0 < M) *(float2*)(outExt + (size_t)r0 * D + c0 + coll) = make_float2(x0, x1);
                if (r1 < M) *(float2*)(outExt + (size_t)r1 * D + c0 + coll) = make_float2(x2, x3);
            }
        }
    }
}

// ------------------------------------------------------------------
extern "C" void kernel_launch(void* const* d_in, const int* in_sizes, int n_in,
                              void* d_out, int out_size) {
    const float* x      = (const float*)d_in[0];
    const int*   ei     = (const int*)d_in[1];
    const int*   et     = (const int*)d_in[2];
    const float* basis1 = (const float*)d_in[3];
    const float* comp1  = (const float*)d_in[4];
    const float* root1  = (const float*)d_in[5];
    const float* bias1  = (const float*)d_in[6];
    const float* basis2 = (const float*)d_in[7];
    const float* comp2  = (const float*)d_in[8];
    const float* root2  = (const float*)d_in[9];
    const float* bias2  = (const float*)d_in[10];
    float* out = (float*)d_out;

    static cudaStream_t s2;
    static cudaEvent_t evFork, evJoin;
    static bool init = false;
    if (!init) {
        cudaStreamCreateWithFlags(&s2, cudaStreamNonBlocking);
        cudaEventCreateWithFlags(&evFork, cudaEventDisableTiming);
        cudaEventCreateWithFlags(&evJoin, cudaEventDisableTiming);
        cudaFuncSetAttribute(gemm_k, cudaFuncAttributeMaxDynamicSharedMemorySize, GSMEM);
        init = true;
    }

    const int T = 256;

    // ---- fork: CSR chain on s2, feature/W packing on main stream ----
    cudaEventRecord(evFork, 0);
    cudaStreamWaitEvent(s2, evFork, 0);

    zero_k<<<(NR8 + T - 1) / T, T, 0, s2>>>();
    count_k<<<(E_EDGES + T - 1) / T, T, 0, s2>>>(ei, et);
    partial8_k<<<NB8, 256, 0, s2>>>();
    scanp8_k<<<1, 512, 0, s2>>>();
    rowptr8_k<<<NB8, 256, 0, s2>>>();
    scatter8_k<<<(E_EDGES + T - 1) / T, T, 0, s2>>>(ei, et);
    cudaEventRecord(evJoin, s2);

    misc_k<<<MISCB, T>>>(x, basis1, root1, basis2, root2);   // main stream

    // ---- join ----
    cudaStreamWaitEvent(0, evJoin, 0);

    dim3 gG(2, (N_NODES + 127) / 128);
    int aggBlocks = (N_NODES * 32 + T - 1) / T;

    // ---------------- layer 1 ----------------
    edge_agg_k<<<aggBlocks, T>>>(comp1, 0);
    gemm_k<<<gG, T, GSMEM>>>(0, nullptr, 1, bias1, N_NODES);

    // ---------------- layer 2 ----------------
    edge_agg_k<<<aggBlocks, T>>>(comp2, 1);
    gemm_k<<<gG, T, GSMEM>>>(1, out, 0, bias2, N_NODES);
}